// round 6
// baseline (speedup 1.0000x reference)
#include <cuda_runtime.h>
#include <cstdint>

// Problem constants
#define Bn 32
#define Dn 1024
#define Hn 1024
#define BETA 0.9f

// Output layout (reference return order):
//   [0, B*H)                 out   = tanh(a)
//   [B*H, 2*B*H)             u_new = a
//   [2*B*H, 2*B*H+B*D*H)     E_w_new = 0.9*E_w + x[i,d]   (broadcast over h)
//   [.., ..+B*H)             E_b_new = 0.9*E_b + 1
// a[i,h] = 0.9*u[i,h] + sum_d x[i,d]*w[d,h] + b[h]

#define NB_GEMM 128            // 32 i-rows * 4 h-chunks of 256
#define NB_EW   760            // one full wave: 148 SMs * 6 blocks - 128
#define NTILES  65536          // half-rows: 512 floats = 128 float4 each
#define OFF_UNEW (Bn*Hn)
#define OFF_EW   (2*Bn*Hn)
#define OFF_EB   (2*Bn*Hn + Bn*Dn*Hn)

#define CP_ASYNC16(dst_u32, src_ptr) \
    asm volatile("cp.async.cg.shared.global [%0], [%1], 16;\n" \
                 :: "r"(dst_u32), "l"(src_ptr) : "memory")
#define CP_COMMIT() asm volatile("cp.async.commit_group;\n" ::: "memory")
#define CP_WAIT(N)  asm volatile("cp.async.wait_group %0;\n" :: "n"(N) : "memory")

__global__ void __launch_bounds__(256, 6)
diag_rtrl_kernel(const float* __restrict__ x,
                 const float* __restrict__ w,
                 const float* __restrict__ b,
                 const float* __restrict__ u,
                 const float* __restrict__ E_w,
                 const float* __restrict__ E_b,
                 float* __restrict__ out)
{
    // 32 KB static smem: 8 warps x 2 buffers x 128 float4 (2 KB stages)
    __shared__ float4 sbuf[2048];

    const int bid = blockIdx.x;
    const int t   = threadIdx.x;

    if (bid < NB_GEMM) {
        // ---- GEMM + tanh + u_new + E_b path ----
        float* xs = reinterpret_cast<float*>(sbuf);  // reuse 4 KB of sbuf
        const int i     = bid >> 2;          // batch row
        const int hbase = (bid & 3) * 256;   // h chunk

        const float4* xr = reinterpret_cast<const float4*>(x + i * Dn);
        reinterpret_cast<float4*>(xs)[t] = xr[t];
        __syncthreads();

        const int h = hbase + t;
        const float* wc = w + h;
        float acc = 0.0f;
        #pragma unroll 8
        for (int d = 0; d < Dn; ++d) {
            acc = fmaf(xs[d], __ldg(wc + d * Hn), acc);
        }

        const int ih = i * Hn + h;
        const float a = fmaf(BETA, u[ih], acc + b[h]);
        out[ih]            = tanhf(a);
        out[OFF_UNEW + ih] = a;
        out[OFF_EB   + ih] = fmaf(BETA, E_b[ih], 1.0f);
        return;
    }

    // ---- E_w streaming via per-warp cp.async double-buffered pipeline ----
    // tile T = half-row: floats [T*512, T*512+512), x row = T>>1.
    const int wid  = t >> 5;
    const int lane = t & 31;
    const int W    = (bid - NB_GEMM) * 8 + wid;   // global stream-warp id
    const int NW   = NB_EW * 8;                   // 6080
    const int n    = (NTILES - 1 - W) / NW + 1;   // tiles for this warp (10..11)

    float4* buf0 = sbuf + wid * 256;
    float4* buf1 = buf0 + 128;
    const uint32_t sb0 = (uint32_t)__cvta_generic_to_shared(buf0) + lane * 16u;
    const uint32_t sb1 = sb0 + 128u * 16u;

    const float4* e4 = reinterpret_cast<const float4*>(E_w);
    float4*       o4 = reinterpret_cast<float4*>(out + OFF_EW);

    // prologue: prefetch stages 0 and 1
    {
        const float4* s = e4 + (size_t)W * 128 + lane;
        CP_ASYNC16(sb0,        s);
        CP_ASYNC16(sb0 + 512,  s + 32);
        CP_ASYNC16(sb0 + 1024, s + 64);
        CP_ASYNC16(sb0 + 1536, s + 96);
        CP_COMMIT();
        if (n > 1) {
            const float4* s2 = e4 + ((size_t)W + NW) * 128 + lane;
            CP_ASYNC16(sb1,        s2);
            CP_ASYNC16(sb1 + 512,  s2 + 32);
            CP_ASYNC16(sb1 + 1024, s2 + 64);
            CP_ASYNC16(sb1 + 1536, s2 + 96);
            CP_COMMIT();
        }
    }

    for (int i = 0; i < n; ++i) {
        const size_t T = (size_t)W + (size_t)i * NW;
        const bool odd = (i & 1);
        float4* cb = odd ? buf1 : buf0;
        const uint32_t cbu = odd ? sb1 : sb0;

        if (i + 1 < n) { CP_WAIT(1); } else { CP_WAIT(0); }

        const float xv = __ldg(x + (int)(T >> 1));

        float4 v0 = cb[lane];
        float4 v1 = cb[32 + lane];
        float4 v2 = cb[64 + lane];
        float4 v3 = cb[96 + lane];

        // refill this buffer with stage i+2 (loads keep streaming during stores)
        if (i + 2 < n) {
            const float4* s = e4 + (T + 2 * (size_t)NW) * 128 + lane;
            CP_ASYNC16(cbu,        s);
            CP_ASYNC16(cbu + 512,  s + 32);
            CP_ASYNC16(cbu + 1024, s + 64);
            CP_ASYNC16(cbu + 1536, s + 96);
            CP_COMMIT();
        }

        float4 r0, r1, r2, r3;
        r0.x = fmaf(BETA, v0.x, xv); r0.y = fmaf(BETA, v0.y, xv);
        r0.z = fmaf(BETA, v0.z, xv); r0.w = fmaf(BETA, v0.w, xv);
        r1.x = fmaf(BETA, v1.x, xv); r1.y = fmaf(BETA, v1.y, xv);
        r1.z = fmaf(BETA, v1.z, xv); r1.w = fmaf(BETA, v1.w, xv);
        r2.x = fmaf(BETA, v2.x, xv); r2.y = fmaf(BETA, v2.y, xv);
        r2.z = fmaf(BETA, v2.z, xv); r2.w = fmaf(BETA, v2.w, xv);
        r3.x = fmaf(BETA, v3.x, xv); r3.y = fmaf(BETA, v3.y, xv);
        r3.z = fmaf(BETA, v3.z, xv); r3.w = fmaf(BETA, v3.w, xv);

        float4* o = o4 + T * 128 + lane;
        __stcs(o,      r0);
        __stcs(o + 32, r1);
        __stcs(o + 64, r2);
        __stcs(o + 96, r3);
    }
}

extern "C" void kernel_launch(void* const* d_in, const int* in_sizes, int n_in,
                              void* d_out, int out_size)
{
    const float* x   = (const float*)d_in[0];   // [32,1024]
    const float* w   = (const float*)d_in[1];   // [1024,1024]
    const float* b   = (const float*)d_in[2];   // [1024]
    const float* u   = (const float*)d_in[3];   // [32,1024]
    const float* E_w = (const float*)d_in[4];   // [1,32,1024,1024]
    const float* E_b = (const float*)d_in[5];   // [1,32,1024]
    float* out = (float*)d_out;

    diag_rtrl_kernel<<<NB_GEMM + NB_EW, 256>>>(x, w, b, u, E_w, E_b, out);
}

// round 7
// speedup vs baseline: 1.0379x; 1.0379x over previous
#include <cuda_runtime.h>
#include <cstdint>

// Problem constants
#define Bn 32
#define Dn 1024
#define Hn 1024
#define BETA 0.9f

// Output layout (reference return order):
//   [0, B*H)              out   = tanh(a)
//   [B*H, 2*B*H)          u_new = a
//   [2*B*H, +B*D*H)       E_w_new = 0.9*E_w + x[i,d]  (broadcast over h)
//   [..., +B*H)           E_b_new = 0.9*E_b + 1
// a[i,h] = 0.9*u[i,h] + sum_d x[i,d]*w[d,h] + b[h]

#define NB_GEMM 128          // 32 i-rows * 4 h-chunks of 256
#define NB_EW   1036         // 7 CTAs/SM * 148 SMs
#define NTILES  16384        // tiles of 2 rows = 2048 floats = 8 KB
#define TILE_BYTES 8192
#define TILE_F4    512
#define OFF_UNEW (Bn*Hn)
#define OFF_EW   (2*Bn*Hn)
#define OFF_EB   (2*Bn*Hn + Bn*Dn*Hn)

// ---- TMA bulk + mbarrier PTX ----
#define BULK_LD(smem_u32, gptr, bytes, mbar_u32)                               \
    asm volatile(                                                              \
        "cp.async.bulk.shared::cluster.global.mbarrier::complete_tx::bytes "   \
        "[%0], [%1], %2, [%3];"                                                \
        :: "r"(smem_u32), "l"(gptr), "r"(bytes), "r"(mbar_u32) : "memory")

#define BULK_ST(gptr, smem_u32, bytes)                                         \
    asm volatile(                                                              \
        "cp.async.bulk.global.shared::cta.bulk_group [%0], [%1], %2;"          \
        :: "l"(gptr), "r"(smem_u32), "r"(bytes) : "memory")

#define BULK_COMMIT() asm volatile("cp.async.bulk.commit_group;" ::: "memory")
#define BULK_WAIT_READ(N) \
    asm volatile("cp.async.bulk.wait_group.read %0;" :: "n"(N) : "memory")
#define BULK_WAIT_ALL() \
    asm volatile("cp.async.bulk.wait_group 0;" ::: "memory")

#define MBAR_INIT(mbar_u32, cnt)                                               \
    asm volatile("mbarrier.init.shared.b64 [%0], %1;"                          \
                 :: "r"(mbar_u32), "r"(cnt) : "memory")
#define MBAR_EXPECT_TX(mbar_u32, bytes)                                        \
    asm volatile("mbarrier.arrive.expect_tx.shared.b64 _, [%0], %1;"           \
                 :: "r"(mbar_u32), "r"(bytes) : "memory")
#define MBAR_WAIT(mbar_u32, parity) do {                                       \
    asm volatile(                                                              \
        "{\n\t.reg .pred P;\n\t"                                               \
        "WL_%=:\n\t"                                                           \
        "mbarrier.try_wait.parity.shared.b64 P, [%0], %1, 0x989680;\n\t"       \
        "@P bra.uni WD_%=;\n\t"                                                \
        "bra.uni WL_%=;\n\t"                                                   \
        "WD_%=:\n\t}"                                                          \
        :: "r"(mbar_u32), "r"(parity) : "memory");                             \
} while (0)

#define FENCE_ASYNC() asm volatile("fence.proxy.async.shared::cta;" ::: "memory")

__global__ void __launch_bounds__(256)
diag_rtrl_kernel(const float* __restrict__ x,
                 const float* __restrict__ w,
                 const float* __restrict__ b,
                 const float* __restrict__ u,
                 const float* __restrict__ E_w,
                 const float* __restrict__ E_b,
                 float* __restrict__ out)
{
    __shared__ alignas(16) float4 s_in[2][TILE_F4];    // 2 x 8 KB
    __shared__ alignas(16) float4 s_out[2][TILE_F4];   // 2 x 8 KB
    __shared__ alignas(8)  unsigned long long s_mbar[2];

    const int bid = blockIdx.x;
    const int t   = threadIdx.x;

    if (bid < NB_GEMM) {
        // ---- GEMM + tanh + u_new + E_b path ----
        float* xs = reinterpret_cast<float*>(&s_in[0][0]);   // reuse 4 KB
        const int i     = bid >> 2;
        const int hbase = (bid & 3) * 256;

        const float4* xr = reinterpret_cast<const float4*>(x + i * Dn);
        reinterpret_cast<float4*>(xs)[t] = xr[t];
        __syncthreads();

        const int h = hbase + t;
        const float* wc = w + h;
        float acc = 0.0f;
        #pragma unroll 16
        for (int d = 0; d < Dn; ++d) {
            acc = fmaf(xs[d], __ldg(wc + d * Hn), acc);
        }

        const int ih = i * Hn + h;
        const float a = fmaf(BETA, u[ih], acc + b[h]);
        out[ih]            = tanhf(a);
        out[OFF_UNEW + ih] = a;
        out[OFF_EB   + ih] = fmaf(BETA, E_b[ih], 1.0f);
        return;
    }

    // ---- E_w streaming: TMA bulk in -> smem compute -> TMA bulk out ----
    const int c = bid - NB_GEMM;                     // 0..NB_EW-1
    const int n = (NTILES - 1 - c) / NB_EW + 1;      // tiles for this CTA

    const uint32_t mb0 = (uint32_t)__cvta_generic_to_shared(&s_mbar[0]);
    const uint32_t mb1 = mb0 + 8;
    const uint32_t in0 = (uint32_t)__cvta_generic_to_shared(&s_in[0][0]);
    const uint32_t in1 = in0 + TILE_BYTES;
    const uint32_t ou0 = (uint32_t)__cvta_generic_to_shared(&s_out[0][0]);
    const uint32_t ou1 = ou0 + TILE_BYTES;

    const char* gin  = reinterpret_cast<const char*>(E_w);
    char*       gout = reinterpret_cast<char*>(out + OFF_EW);

    if (t == 0) {
        MBAR_INIT(mb0, 1);
        MBAR_INIT(mb1, 1);
        FENCE_ASYNC();
    }
    __syncthreads();

    // prologue: prefetch tiles 0 and 1
    if (t == 0) {
        MBAR_EXPECT_TX(mb0, TILE_BYTES);
        BULK_LD(in0, gin + (size_t)c * TILE_BYTES, TILE_BYTES, mb0);
        if (n > 1) {
            MBAR_EXPECT_TX(mb1, TILE_BYTES);
            BULK_LD(in1, gin + ((size_t)c + NB_EW) * TILE_BYTES, TILE_BYTES, mb1);
        }
    }

    for (int i = 0; i < n; ++i) {
        const size_t gt = (size_t)c + (size_t)i * NB_EW;   // global tile id
        const int s = i & 1;
        const uint32_t inS = s ? in1 : in0;
        const uint32_t ouS = s ? ou1 : ou0;
        const uint32_t mbS = s ? mb1 : mb0;

        // wait tile data
        MBAR_WAIT(mbS, (i >> 1) & 1);

        // ensure out-stage s is no longer being read by TMA (store from i-2)
        if (t == 0) { BULK_WAIT_READ(1); }
        __syncthreads();

        // compute: 2 rows per tile; thread t handles f4 t (row 0) and t+256 (row 1)
        const float xv0 = __ldg(x + 2 * gt);
        const float xv1 = __ldg(x + 2 * gt + 1);
        float4* inp = s ? &s_in[1][0]  : &s_in[0][0];
        float4* oup = s ? &s_out[1][0] : &s_out[0][0];

        float4 v0 = inp[t];
        float4 v1 = inp[t + 256];
        float4 r0, r1;
        r0.x = fmaf(BETA, v0.x, xv0); r0.y = fmaf(BETA, v0.y, xv0);
        r0.z = fmaf(BETA, v0.z, xv0); r0.w = fmaf(BETA, v0.w, xv0);
        r1.x = fmaf(BETA, v1.x, xv1); r1.y = fmaf(BETA, v1.y, xv1);
        r1.z = fmaf(BETA, v1.z, xv1); r1.w = fmaf(BETA, v1.w, xv1);
        oup[t]       = r0;
        oup[t + 256] = r1;

        __syncthreads();   // all STS done; all LDS of in[s] done

        if (t == 0) {
            FENCE_ASYNC();                                   // STS -> async proxy
            BULK_ST(gout + gt * TILE_BYTES, ouS, TILE_BYTES);
            BULK_COMMIT();
            if (i + 2 < n) {                                 // refill in[s]
                MBAR_EXPECT_TX(mbS, TILE_BYTES);
                BULK_LD(inS, gin + (gt + 2 * (size_t)NB_EW) * TILE_BYTES,
                        TILE_BYTES, mbS);
            }
        }
    }

    // drain all outstanding bulk stores before exit
    if (t == 0) { BULK_WAIT_ALL(); }
}

extern "C" void kernel_launch(void* const* d_in, const int* in_sizes, int n_in,
                              void* d_out, int out_size)
{
    const float* x   = (const float*)d_in[0];   // [32,1024]
    const float* w   = (const float*)d_in[1];   // [1024,1024]
    const float* b   = (const float*)d_in[2];   // [1024]
    const float* u   = (const float*)d_in[3];   // [32,1024]
    const float* E_w = (const float*)d_in[4];   // [1,32,1024,1024]
    const float* E_b = (const float*)d_in[5];   // [1,32,1024]
    float* out = (float*)d_out;

    diag_rtrl_kernel<<<NB_GEMM + NB_EW, 256>>>(x, w, b, u, E_w, E_b, out);
}

// round 8
// speedup vs baseline: 2.1642x; 2.0851x over previous
#include <cuda_runtime.h>
#include <cstdint>

// Problem constants
#define Bn 32
#define Dn 1024
#define Hn 1024
#define BETA 0.9f

// Output layout (reference return order):
//   [0, B*H)              out   = tanh(a)
//   [B*H, 2*B*H)          u_new = a
//   [2*B*H, +B*D*H)       E_w_new = 0.9*E_w + x[i,d]  (broadcast over h)
//   [..., +B*H)           E_b_new = 0.9*E_b + 1
// a[i,h] = 0.9*u[i,h] + sum_d x[i,d]*w[d,h] + b[h]

#define NB_GEMM 128          // 32 i-rows * 4 h-chunks of 256
#define NB_EW   316          // single co-resident wave: 148*3 - 128
#define NWARPS  (NB_EW * 8)  // 2528 stream warps
#define ROWS    (Bn * Dn)    // 32768 rows of H=1024 floats
#define OFF_UNEW (Bn*Hn)
#define OFF_EW   (2*Bn*Hn)
#define OFF_EB   (2*Bn*Hn + Bn*Dn*Hn)

// row r: float4 index r*256 + k*32 + lane, k=0..7
#define LOADB(arr, r)                                                   \
    do { const float4* _s = e4 + (size_t)(r) * 256 + lane;              \
         _Pragma("unroll")                                              \
         for (int _k = 0; _k < 8; ++_k) arr[_k] = __ldcs(_s + _k * 32); \
    } while (0)

#define STOREB(arr, r, xv)                                              \
    do { float4* _o = o4 + (size_t)(r) * 256 + lane;                    \
         _Pragma("unroll")                                              \
         for (int _k = 0; _k < 8; ++_k) {                               \
             float4 _v;                                                 \
             _v.x = fmaf(BETA, arr[_k].x, xv);                          \
             _v.y = fmaf(BETA, arr[_k].y, xv);                          \
             _v.z = fmaf(BETA, arr[_k].z, xv);                          \
             _v.w = fmaf(BETA, arr[_k].w, xv);                          \
             __stcs(_o + _k * 32, _v);                                  \
         }                                                              \
    } while (0)

__global__ void __launch_bounds__(256)
diag_rtrl_kernel(const float* __restrict__ x,
                 const float* __restrict__ w,
                 const float* __restrict__ b,
                 const float* __restrict__ u,
                 const float* __restrict__ E_w,
                 const float* __restrict__ E_b,
                 float* __restrict__ out)
{
    __shared__ float xs[Dn];   // GEMM path only (4 KB)

    const int bid = blockIdx.x;
    const int t   = threadIdx.x;

    if (bid < NB_GEMM) {
        // ---- GEMM + tanh + u_new + E_b path ----
        const int i     = bid >> 2;          // batch row
        const int hbase = (bid & 3) * 256;   // h chunk

        const float4* xr = reinterpret_cast<const float4*>(x + i * Dn);
        reinterpret_cast<float4*>(xs)[t] = xr[t];
        __syncthreads();

        const int h = hbase + t;
        const float* wc = w + h;
        float acc = 0.0f;
        #pragma unroll 16
        for (int d = 0; d < Dn; ++d) {
            acc = fmaf(xs[d], __ldg(wc + d * Hn), acc);
        }

        const int ih = i * Hn + h;
        const float a = fmaf(BETA, u[ih], acc + b[h]);
        out[ih]            = tanhf(a);
        out[OFF_UNEW + ih] = a;
        out[OFF_EB   + ih] = fmaf(BETA, E_b[ih], 1.0f);
        return;
    }

    // ---- E_w streaming: persistent warps, batch-pipelined ----
    const int lane = t & 31;
    const int W    = (bid - NB_GEMM) * 8 + (t >> 5);   // global stream warp id
    const int n    = (ROWS - 1 - W) / NWARPS + 1;      // rows for this warp (12-13)

    const float4* e4 = reinterpret_cast<const float4*>(E_w);
    float4*       o4 = reinterpret_cast<float4*>(out + OFF_EW);

    float4 A[8], Bv[8];
    size_t r  = (size_t)W;
    float  xA = __ldg(x + r);
    LOADB(A, r);

    size_t rp = r;          // row whose data is pending in the active buffer
    float  xB;
    bool   pa = true;       // pending buffer is A?

    for (int i = 1; i < n; ++i) {
        const size_t rn = (size_t)W + (size_t)i * NWARPS;
        if (pa) {
            xB = __ldg(x + rn);
            LOADB(Bv, rn);          // 8 loads in flight...
            STOREB(A, rp, xA);      // ...while draining previous row
        } else {
            xA = __ldg(x + rn);
            LOADB(A, rn);
            STOREB(Bv, rp, xB);
        }
        rp = rn;
        pa = !pa;
    }
    if (pa) { STOREB(A, rp, xA); } else { STOREB(Bv, rp, xB); }
}

extern "C" void kernel_launch(void* const* d_in, const int* in_sizes, int n_in,
                              void* d_out, int out_size)
{
    const float* x   = (const float*)d_in[0];   // [32,1024]
    const float* w   = (const float*)d_in[1];   // [1024,1024]
    const float* b   = (const float*)d_in[2];   // [1024]
    const float* u   = (const float*)d_in[3];   // [32,1024]
    const float* E_w = (const float*)d_in[4];   // [1,32,1024,1024]
    const float* E_b = (const float*)d_in[5];   // [1,32,1024]
    float* out = (float*)d_out;

    diag_rtrl_kernel<<<NB_GEMM + NB_EW, 256>>>(x, w, b, u, E_w, E_b, out);
}